// round 12
// baseline (speedup 1.0000x reference)
#include <cuda_runtime.h>
#include <cuda_bf16.h>

// ---------------------------------------------------------------------------
// AttnReadout: fused GNN attention readout.
//   K1: p[g,h] = BN(feat[last[g]]) @ W_i + intend[g] @ W_v + b_i + b_v
//   K2: per-graph fused: u = BN(feat_g) @ W_u ; e = sigmoid(u + p[g]) @ W_e ;
//       softmax over 50 nodes ; out[g] = alpha^T @ BN(feat_g)
// Shapes fixed by the dataset: N=500000, B=10000, D=H=256, nodes/graph=50.
//
// R11: 512-thread CTA per graph, 2h x 14node fragments, vbuf -> pbuf partials.
//      smem 105KB -> 80KB, occ 25% -> 50% (R10 showed issue=53% @ occ 25%:
//      latency-bound, not pipe-bound).
// ---------------------------------------------------------------------------

#define DCONST 256
#define HCONST 256
#define NPG    50
#define FSTR   52              // fT row stride in floats (208B = 13*16B)
#define PBSTR  132             // pbuf row stride (pad: 12*132 mod 32 != 0)
#define MAXB   10000

// per-graph vector scratch (10.24 MB) — device global (no allocations allowed)
__device__ float g_pg[MAXB * HCONST];

__device__ __forceinline__ unsigned long long pk2(float lo, float hi) {
    unsigned long long r;
    asm("mov.b64 %0, {%1, %2};" : "=l"(r) : "f"(lo), "f"(hi));
    return r;
}
__device__ __forceinline__ void unpk2(unsigned long long v, float& lo, float& hi) {
    asm("mov.b64 {%0, %1}, %2;" : "=f"(lo), "=f"(hi) : "l"(v));
}
#define FMA2(acc, a, b) \
    asm("fma.rn.f32x2 %0, %1, %2, %0;" : "+l"(acc) : "l"(a), "l"(b))

// ---------------------------------------------------------------------------
// K1: per-graph gate vector. 32 graphs per CTA, 256 threads.
// (unchanged from R10 — ~7% of total time)
// ---------------------------------------------------------------------------
#define K1_ROWS 32
#define K1_STR  36

__global__ void __launch_bounds__(256, 2) pergraph_kernel(
    const float* __restrict__ feat, const float* __restrict__ intend,
    const int* __restrict__ last_nodes,
    const float* __restrict__ W_v, const float* __restrict__ b_v,
    const float* __restrict__ W_i, const float* __restrict__ b_i,
    const float* __restrict__ bn_g, const float* __restrict__ bn_b,
    const float* __restrict__ bn_m, const float* __restrict__ bn_v,
    int B)
{
    extern __shared__ float sm[];
    float* AT = sm;  // [2*DCONST][K1_STR]

    const int t  = threadIdx.x;
    const int g0 = blockIdx.x * K1_ROWS;
    const int nrows = min(K1_ROWS, B - g0);

    {
        const float scale = bn_g[t] * rsqrtf(bn_v[t] + 1e-5f);
        const float shift = bn_b[t] - bn_m[t] * scale;
        for (int r = 0; r < K1_ROWS; ++r) {
            float fv = 0.f, iv = 0.f;
            if (r < nrows) {
                const int g = g0 + r;
                fv = feat[(size_t)last_nodes[g] * DCONST + t] * scale + shift;
                iv = intend[(size_t)g * DCONST + t];
            }
            AT[t * K1_STR + r]            = fv;
            AT[(DCONST + t) * K1_STR + r] = iv;
        }
    }
    __syncthreads();

    const int hh    = t & 127;
    const int half  = t >> 7;
    const int h0    = 2 * hh;
    const int rbase = half * 16;

    const float bias0 = b_i[h0]     + b_v[h0];
    const float bias1 = b_i[h0 + 1] + b_v[h0 + 1];

    unsigned long long acc0[8], acc1[8];
    {
        const unsigned long long b20 = pk2(bias0, bias0);
        const unsigned long long b21 = pk2(bias1, bias1);
        #pragma unroll
        for (int j = 0; j < 8; ++j) { acc0[j] = b20; acc1[j] = b21; }
    }

    {
        const float2* Wi2 = (const float2*)W_i;
        float2 wn = Wi2[hh];
        #pragma unroll 1
        for (int k = 0; k < DCONST; ++k) {
            const float2 w = wn;
            if (k + 1 < DCONST) wn = Wi2[(k + 1) * 128 + hh];
            const unsigned long long w20 = pk2(w.x, w.x);
            const unsigned long long w21 = pk2(w.y, w.y);
            const ulonglong2* row = (const ulonglong2*)(AT + k * K1_STR + rbase);
            #pragma unroll
            for (int jj = 0; jj < 4; ++jj) {
                ulonglong2 q = row[jj];
                FMA2(acc0[2 * jj],     q.x, w20);
                FMA2(acc1[2 * jj],     q.x, w21);
                FMA2(acc0[2 * jj + 1], q.y, w20);
                FMA2(acc1[2 * jj + 1], q.y, w21);
            }
        }
    }
    {
        const float2* Wv2 = (const float2*)W_v;
        float2 wn = Wv2[hh];
        #pragma unroll 1
        for (int k = 0; k < DCONST; ++k) {
            const float2 w = wn;
            if (k + 1 < DCONST) wn = Wv2[(k + 1) * 128 + hh];
            const unsigned long long w20 = pk2(w.x, w.x);
            const unsigned long long w21 = pk2(w.y, w.y);
            const ulonglong2* row = (const ulonglong2*)(AT + (DCONST + k) * K1_STR + rbase);
            #pragma unroll
            for (int jj = 0; jj < 4; ++jj) {
                ulonglong2 q = row[jj];
                FMA2(acc0[2 * jj],     q.x, w20);
                FMA2(acc1[2 * jj],     q.x, w21);
                FMA2(acc0[2 * jj + 1], q.y, w20);
                FMA2(acc1[2 * jj + 1], q.y, w21);
            }
        }
    }

    #pragma unroll
    for (int j = 0; j < 8; ++j) {
        float a0, b0, a1, b1;
        unpk2(acc0[j], a0, b0);
        unpk2(acc1[j], a1, b1);
        const int r = rbase + 2 * j;
        if (r < nrows)
            *(float2*)(g_pg + (size_t)(g0 + r) * HCONST + h0) = make_float2(a0, a1);
        if (r + 1 < nrows)
            *(float2*)(g_pg + (size_t)(g0 + r + 1) * HCONST + h0) = make_float2(b0, b1);
    }
}

// ---------------------------------------------------------------------------
// K2: one CTA per graph, 512 threads.
// GEMM mapping: nq = t&3 (node quarter, nbase = 12*nq, 14 nodes each with
// 2-node overlaps -> duplicated identical work, benign), hh = t>>2 (h pair).
// SMEM: fT[256][52] + pbuf[50][132] partial e-sums + softmax scratch. ~80KB.
// ---------------------------------------------------------------------------
__global__ void __launch_bounds__(512, 2) attn_main_kernel(
    const float* __restrict__ feat,
    const float* __restrict__ W_u, const float* __restrict__ W_e,
    const float* __restrict__ bn_g, const float* __restrict__ bn_b,
    const float* __restrict__ bn_m, const float* __restrict__ bn_v,
    float* __restrict__ out)
{
    extern __shared__ float sm[];
    float* fT      = sm;                          // 256*52 = 13312 floats
    float* pbuf    = sm + DCONST * FSTR;          // 50*132 = 6600 floats
    float* e_s     = pbuf + NPG * PBSTR;          // 64
    float* alpha_s = e_s + 64;                    // 64

    const int t = threadIdx.x;
    const int g = blockIdx.x;
    const int lane = t & 31;
    const int warp = t >> 5;

    // ---- load + BN + transpose: 512 threads, f = t&255, node half = t>>8 ----
    {
        const int f  = t & 255;
        const int nh = t >> 8;
        const float scale = bn_g[f] * rsqrtf(bn_v[f] + 1e-5f);
        const float shift = bn_b[f] - bn_m[f] * scale;
        const float* fbase = feat + (size_t)g * NPG * DCONST;
        const int n0 = nh * 25;
        #pragma unroll
        for (int j = 0; j < 25; ++j) {
            const int n = n0 + j;
            fT[f * FSTR + n] = fbase[n * DCONST + f] * scale + shift;
        }
    }
    __syncthreads();

    // ---- GEMM: 2 h-columns x 14 nodes per thread ----
    const int nq    = t & 3;
    const int hh    = t >> 2;          // 0..127
    const int h0    = 2 * hh;
    const int nbase = nq * 12;         // 0,12,24,36 (48B-aligned)

    const float2 p2  = *(const float2*)(g_pg + (size_t)g * HCONST + h0);
    const float2 we2 = *(const float2*)(W_e + h0);

    unsigned long long acc0[7], acc1[7];
    #pragma unroll
    for (int j = 0; j < 7; ++j) { acc0[j] = 0ull; acc1[j] = 0ull; }

    {
        const float2* Wu2 = (const float2*)W_u;
        float2 wcur  = Wu2[hh];
        float2 wnext = Wu2[128 + hh];
        #pragma unroll 1
        for (int k = 0; k < DCONST; ++k) {
            const float2 w = wcur;
            wcur = wnext;
            if (k + 2 < DCONST) wnext = Wu2[(k + 2) * 128 + hh];
            const unsigned long long wa = pk2(w.x, w.x);
            const unsigned long long wb = pk2(w.y, w.y);
            const ulonglong2* row = (const ulonglong2*)(fT + k * FSTR + nbase);
            ulonglong2 q0 = row[0], q1 = row[1], q2 = row[2], q3 = row[3];
            FMA2(acc0[0], q0.x, wa); FMA2(acc1[0], q0.x, wb);
            FMA2(acc0[1], q0.y, wa); FMA2(acc1[1], q0.y, wb);
            FMA2(acc0[2], q1.x, wa); FMA2(acc1[2], q1.x, wb);
            FMA2(acc0[3], q1.y, wa); FMA2(acc1[3], q1.y, wb);
            FMA2(acc0[4], q2.x, wa); FMA2(acc1[4], q2.x, wb);
            FMA2(acc0[5], q2.y, wa); FMA2(acc1[5], q2.y, wb);
            FMA2(acc0[6], q3.x, wa); FMA2(acc1[6], q3.x, wb);
        }
    }

    // ---- epilogue: pbuf[n][hh] = sig(u(h0)+p)*we(h0) + sig(u(h1)+p)*we(h1) ----
    #pragma unroll
    for (int j = 0; j < 7; ++j) {
        float ua0, ua1, ub0, ub1;
        unpk2(acc0[j], ua0, ua1);   // h0:   nodes nbase+2j, nbase+2j+1
        unpk2(acc1[j], ub0, ub1);   // h0+1: same nodes
        const int n = nbase + 2 * j;
        {
            const float va = __fdividef(we2.x, 1.f + __expf(-(ua0 + p2.x)));
            const float vb = __fdividef(we2.y, 1.f + __expf(-(ub0 + p2.y)));
            pbuf[n * PBSTR + hh] = va + vb;
        }
        {
            const float va = __fdividef(we2.x, 1.f + __expf(-(ua1 + p2.x)));
            const float vb = __fdividef(we2.y, 1.f + __expf(-(ub1 + p2.y)));
            pbuf[(n + 1) * PBSTR + hh] = va + vb;
        }
    }
    __syncthreads();

    // ---- e[n] = sum_{hh} pbuf[n][hh]; 16 warps, warp w -> rows w, w+16, ... ----
    for (int n = warp; n < NPG; n += 16) {
        float s = pbuf[n * PBSTR + lane]      + pbuf[n * PBSTR + lane + 32]
                + pbuf[n * PBSTR + lane + 64] + pbuf[n * PBSTR + lane + 96];
        #pragma unroll
        for (int off = 16; off > 0; off >>= 1)
            s += __shfl_xor_sync(0xffffffffu, s, off);
        if (lane == 0) e_s[n] = s;
    }
    __syncthreads();

    // ---- segment softmax over NPG=50 values (warp 0) ----
    if (warp == 0) {
        const float NEG = -3.402823466e38f;
        float a = e_s[lane];
        float b = (lane + 32 < NPG) ? e_s[lane + 32] : NEG;
        float m = fmaxf(a, b);
        #pragma unroll
        for (int off = 16; off > 0; off >>= 1)
            m = fmaxf(m, __shfl_xor_sync(0xffffffffu, m, off));
        float ea = __expf(a - m);
        float eb = (lane + 32 < NPG) ? __expf(b - m) : 0.f;
        float s = ea + eb;
        #pragma unroll
        for (int off = 16; off > 0; off >>= 1)
            s += __shfl_xor_sync(0xffffffffu, s, off);
        const float inv = __fdividef(1.f, s);
        alpha_s[lane] = ea * inv;
        if (lane + 32 < NPG) alpha_s[lane + 32] = eb * inv;
    }
    __syncthreads();

    // ---- readout: out[g][f] = sum_n alpha[n] * fT[f][n]  (threads 0..255) ----
    if (t < 256) {
        float r = 0.f;
        const float4* myrow = (const float4*)(fT + t * FSTR);
        const float4* al4   = (const float4*)alpha_s;
        #pragma unroll
        for (int jj = 0; jj < 12; ++jj) {
            float4 q = myrow[jj];
            float4 a = al4[jj];
            r += q.x * a.x + q.y * a.y + q.z * a.z + q.w * a.w;
        }
        r += fT[t * FSTR + 48] * alpha_s[48];
        r += fT[t * FSTR + 49] * alpha_s[49];
        out[(size_t)g * HCONST + t] = r;
    }
}

// ---------------------------------------------------------------------------
extern "C" void kernel_launch(void* const* d_in, const int* in_sizes, int n_in,
                              void* d_out, int out_size)
{
    const float* feat       = (const float*)d_in[0];
    const float* intend     = (const float*)d_in[1];
    const int*   last_nodes = (const int*)d_in[2];
    // d_in[3] segment_ids: unused (graphs are contiguous, equal-sized)
    const float* W_u  = (const float*)d_in[4];
    const float* W_v  = (const float*)d_in[5];
    const float* b_v  = (const float*)d_in[6];
    const float* W_i  = (const float*)d_in[7];
    const float* b_i  = (const float*)d_in[8];
    const float* W_e  = (const float*)d_in[9];
    const float* bn_g = (const float*)d_in[10];
    const float* bn_b = (const float*)d_in[11];
    const float* bn_m = (const float*)d_in[12];
    const float* bn_v = (const float*)d_in[13];
    float* out = (float*)d_out;

    const int B = in_sizes[1] / HCONST;   // 10000

    const size_t smem1 = (size_t)(2 * DCONST) * K1_STR * sizeof(float);  // ~72 KB
    const size_t smem2 = (size_t)(DCONST * FSTR + NPG * PBSTR + 128) * sizeof(float); // ~80 KB

    cudaFuncSetAttribute(pergraph_kernel,
                         cudaFuncAttributeMaxDynamicSharedMemorySize, (int)smem1);
    cudaFuncSetAttribute(attn_main_kernel,
                         cudaFuncAttributeMaxDynamicSharedMemorySize, (int)smem2);

    const int nblk1 = (B + K1_ROWS - 1) / K1_ROWS;
    pergraph_kernel<<<nblk1, 256, smem1>>>(feat, intend, last_nodes,
                                           W_v, b_v, W_i, b_i,
                                           bn_g, bn_b, bn_m, bn_v, B);

    attn_main_kernel<<<B, 512, smem2>>>(feat, W_u, W_e,
                                        bn_g, bn_b, bn_m, bn_v, out);
}

// round 14
// speedup vs baseline: 1.4390x; 1.4390x over previous
#include <cuda_runtime.h>
#include <cuda_bf16.h>

// ---------------------------------------------------------------------------
// AttnReadout: fused GNN attention readout.
//   K1: p[g,h] = BN(feat[last[g]]) @ W_i + intend[g] @ W_v + b_i + b_v
//   K2: per-graph fused: u = BN(feat_g) @ W_u ; e = sigmoid(u + p[g]) @ W_e ;
//       softmax over 50 nodes ; out[g] = alpha^T @ BN(feat_g)
// Shapes fixed by the dataset: N=500000, B=10000, D=H=256, nodes/graph=50.
//
// R14 (= R13 rerun; prior bench was an infra failure, kernel never executed):
//   R6 inner loop (2h x 28node, warp-uniform broadcast LDS) + shuffle-based
//   e-reduction (vbuf 50KB -> pbuf 0.9KB) -> smem 105KB -> 54.4KB -> 3 CTAs
//   per SM (24 warps). R10/R12 showed the body is issue-starved at 16 warps
//   and reg-starved at 512 threads; this keeps the good body, adds warps.
// ---------------------------------------------------------------------------

#define DCONST 256
#define HCONST 256
#define NPG    50
#define FSTR   52              // fT row stride in floats (208B = 13*16B)
#define MAXB   10000

// per-graph vector scratch (10.24 MB) — device global (no allocations allowed)
__device__ float g_pg[MAXB * HCONST];

__device__ __forceinline__ unsigned long long pk2(float lo, float hi) {
    unsigned long long r;
    asm("mov.b64 %0, {%1, %2};" : "=l"(r) : "f"(lo), "f"(hi));
    return r;
}
__device__ __forceinline__ void unpk2(unsigned long long v, float& lo, float& hi) {
    asm("mov.b64 {%0, %1}, %2;" : "=f"(lo), "=f"(hi) : "l"(v));
}
#define FMA2(acc, a, b) \
    asm("fma.rn.f32x2 %0, %1, %2, %0;" : "+l"(acc) : "l"(a), "l"(b))
#define ADDF2(out, a, b) \
    asm("add.rn.f32x2 %0, %1, %2;" : "=l"(out) : "l"(a), "l"(b))

// ---------------------------------------------------------------------------
// K1: per-graph gate vector. 32 graphs per CTA, 256 threads. (unchanged)
// ---------------------------------------------------------------------------
#define K1_ROWS 32
#define K1_STR  36

__global__ void __launch_bounds__(256, 2) pergraph_kernel(
    const float* __restrict__ feat, const float* __restrict__ intend,
    const int* __restrict__ last_nodes,
    const float* __restrict__ W_v, const float* __restrict__ b_v,
    const float* __restrict__ W_i, const float* __restrict__ b_i,
    const float* __restrict__ bn_g, const float* __restrict__ bn_b,
    const float* __restrict__ bn_m, const float* __restrict__ bn_v,
    int B)
{
    extern __shared__ float sm[];
    float* AT = sm;  // [2*DCONST][K1_STR]

    const int t  = threadIdx.x;
    const int g0 = blockIdx.x * K1_ROWS;
    const int nrows = min(K1_ROWS, B - g0);

    {
        const float scale = bn_g[t] * rsqrtf(bn_v[t] + 1e-5f);
        const float shift = bn_b[t] - bn_m[t] * scale;
        for (int r = 0; r < K1_ROWS; ++r) {
            float fv = 0.f, iv = 0.f;
            if (r < nrows) {
                const int g = g0 + r;
                fv = feat[(size_t)last_nodes[g] * DCONST + t] * scale + shift;
                iv = intend[(size_t)g * DCONST + t];
            }
            AT[t * K1_STR + r]            = fv;
            AT[(DCONST + t) * K1_STR + r] = iv;
        }
    }
    __syncthreads();

    const int hh    = t & 127;
    const int half  = t >> 7;
    const int h0    = 2 * hh;
    const int rbase = half * 16;

    const float bias0 = b_i[h0]     + b_v[h0];
    const float bias1 = b_i[h0 + 1] + b_v[h0 + 1];

    unsigned long long acc0[8], acc1[8];
    {
        const unsigned long long b20 = pk2(bias0, bias0);
        const unsigned long long b21 = pk2(bias1, bias1);
        #pragma unroll
        for (int j = 0; j < 8; ++j) { acc0[j] = b20; acc1[j] = b21; }
    }

    {
        const float2* Wi2 = (const float2*)W_i;
        float2 wn = Wi2[hh];
        #pragma unroll 1
        for (int k = 0; k < DCONST; ++k) {
            const float2 w = wn;
            if (k + 1 < DCONST) wn = Wi2[(k + 1) * 128 + hh];
            const unsigned long long w20 = pk2(w.x, w.x);
            const unsigned long long w21 = pk2(w.y, w.y);
            const ulonglong2* row = (const ulonglong2*)(AT + k * K1_STR + rbase);
            #pragma unroll
            for (int jj = 0; jj < 4; ++jj) {
                ulonglong2 q = row[jj];
                FMA2(acc0[2 * jj],     q.x, w20);
                FMA2(acc1[2 * jj],     q.x, w21);
                FMA2(acc0[2 * jj + 1], q.y, w20);
                FMA2(acc1[2 * jj + 1], q.y, w21);
            }
        }
    }
    {
        const float2* Wv2 = (const float2*)W_v;
        float2 wn = Wv2[hh];
        #pragma unroll 1
        for (int k = 0; k < DCONST; ++k) {
            const float2 w = wn;
            if (k + 1 < DCONST) wn = Wv2[(k + 1) * 128 + hh];
            const unsigned long long w20 = pk2(w.x, w.x);
            const unsigned long long w21 = pk2(w.y, w.y);
            const ulonglong2* row = (const ulonglong2*)(AT + (DCONST + k) * K1_STR + rbase);
            #pragma unroll
            for (int jj = 0; jj < 4; ++jj) {
                ulonglong2 q = row[jj];
                FMA2(acc0[2 * jj],     q.x, w20);
                FMA2(acc1[2 * jj],     q.x, w21);
                FMA2(acc0[2 * jj + 1], q.y, w20);
                FMA2(acc1[2 * jj + 1], q.y, w21);
            }
        }
    }

    #pragma unroll
    for (int j = 0; j < 8; ++j) {
        float a0, b0, a1, b1;
        unpk2(acc0[j], a0, b0);
        unpk2(acc1[j], a1, b1);
        const int r = rbase + 2 * j;
        if (r < nrows)
            *(float2*)(g_pg + (size_t)(g0 + r) * HCONST + h0) = make_float2(a0, a1);
        if (r + 1 < nrows)
            *(float2*)(g_pg + (size_t)(g0 + r + 1) * HCONST + h0) = make_float2(b0, b1);
    }
}

// ---------------------------------------------------------------------------
// K2: one CTA per graph, 256 threads, 3 CTAs/SM.
// Thread (hh = t&127, half = t>>7): h = {2hh, 2hh+1}, nodes nbase..nbase+27
// (nbase = 24*half; nodes 24..27 duplicated across halves — identical values,
// only half 0's copy is consumed; nodes 50,51 are zero pad).
// Warps 0-3 = half 0, warps 4-7 = half 1; within a warp nbase is uniform, so
// every fT LDS.128 is a pure 32-lane broadcast.
// e-reduction: per-warp f32x2 butterfly (no vbuf). SMEM ~54.4 KB.
// ---------------------------------------------------------------------------
__global__ void __launch_bounds__(256, 3) attn_main_kernel(
    const float* __restrict__ feat,
    const float* __restrict__ W_u, const float* __restrict__ W_e,
    const float* __restrict__ bn_g, const float* __restrict__ bn_b,
    const float* __restrict__ bn_m, const float* __restrict__ bn_v,
    float* __restrict__ out)
{
    extern __shared__ float sm[];
    float* fT      = sm;                     // 256*52 = 13312 floats (53248 B)
    float* pbuf    = sm + DCONST * FSTR;     // [8 warps][28 nodes] = 224 floats
    float* alpha_s = pbuf + 8 * 28;          // 64 floats

    const int t = threadIdx.x;
    const int g = blockIdx.x;
    const int lane = t & 31;
    const int warp = t >> 5;

    // ---- load + BN + transpose (t = feature index) ----
    {
        const float scale = bn_g[t] * rsqrtf(bn_v[t] + 1e-5f);
        const float shift = bn_b[t] - bn_m[t] * scale;
        const float* fbase = feat + (size_t)g * NPG * DCONST;
        #pragma unroll
        for (int n = 0; n < NPG; ++n) {
            fT[t * FSTR + n] = fbase[n * DCONST + t] * scale + shift;
        }
        fT[t * FSTR + 50] = 0.f;
        fT[t * FSTR + 51] = 0.f;
    }
    __syncthreads();

    // ---- GEMM: 2 h-columns x 28 nodes per thread ----
    const int hh    = t & 127;
    const int half  = t >> 7;
    const int h0    = 2 * hh;
    const int nbase = half * 24;        // 0 or 24 (96B, 16B-aligned)

    const float2 p2  = *(const float2*)(g_pg + (size_t)g * HCONST + h0);
    const float2 we2 = *(const float2*)(W_e + h0);

    unsigned long long acc0[14], acc1[14];
    #pragma unroll
    for (int j = 0; j < 14; ++j) { acc0[j] = 0ull; acc1[j] = 0ull; }

    {
        const float2* Wu2 = (const float2*)W_u;
        float2 wn = Wu2[hh];
        #pragma unroll 1
        for (int k = 0; k < DCONST; ++k) {
            const float2 w = wn;
            if (k + 1 < DCONST) wn = Wu2[(k + 1) * 128 + hh];
            const unsigned long long wa = pk2(w.x, w.x);
            const unsigned long long wb = pk2(w.y, w.y);
            const ulonglong2* row = (const ulonglong2*)(fT + k * FSTR + nbase);
            #pragma unroll
            for (int jj = 0; jj < 7; ++jj) {
                ulonglong2 q = row[jj];
                FMA2(acc0[2 * jj], q.x, wa);
                FMA2(acc1[2 * jj], q.x, wb);
                if (jj < 6) {
                    FMA2(acc0[2 * jj + 1], q.y, wa);
                    FMA2(acc1[2 * jj + 1], q.y, wb);
                } else {
                    FMA2(acc0[13], q.y, wa);
                    FMA2(acc1[13], q.y, wb);
                }
            }
        }
    }

    // ---- epilogue: per-node v = sig(u(h0)+p)*we(h0) + sig(u(h1)+p)*we(h1),
    //      packed as f32x2 (node pair), then 32-lane butterfly sum over hh ----
    unsigned long long vv[14];
    #pragma unroll
    for (int j = 0; j < 14; ++j) {
        float ua0, ua1, ub0, ub1;
        unpk2(acc0[j], ua0, ua1);   // h0:   nodes nbase+2j, nbase+2j+1
        unpk2(acc1[j], ub0, ub1);   // h0+1: same nodes
        const float s0 = __fdividef(we2.x, 1.f + __expf(-(ua0 + p2.x)))
                       + __fdividef(we2.y, 1.f + __expf(-(ub0 + p2.y)));
        const float s1 = __fdividef(we2.x, 1.f + __expf(-(ua1 + p2.x)))
                       + __fdividef(we2.y, 1.f + __expf(-(ub1 + p2.y)));
        vv[j] = pk2(s0, s1);
    }
    #pragma unroll
    for (int off = 16; off > 0; off >>= 1) {
        #pragma unroll
        for (int j = 0; j < 14; ++j) {
            unsigned long long o = __shfl_xor_sync(0xffffffffu, vv[j], off);
            ADDF2(vv[j], vv[j], o);
        }
    }
    if (lane == 0) {
        float2* dst = (float2*)(pbuf + warp * 28);
        #pragma unroll
        for (int j = 0; j < 14; ++j) {
            float s0, s1;
            unpk2(vv[j], s0, s1);
            dst[j] = make_float2(s0, s1);
        }
    }
    __syncthreads();

    // ---- softmax over 50 nodes (warp 0) ----
    // e[n] = n<28 ? sum_{w=0..3} pbuf[w][n] : sum_{w=4..7} pbuf[w][n-24]
    if (warp == 0) {
        const float NEG = -3.402823466e38f;
        float a, b;
        {
            const int n = lane;                      // 0..31
            const int j = (n < 28) ? n : (n - 24);
            const int w0 = (n < 28) ? 0 : 4;
            a = pbuf[(w0 + 0) * 28 + j] + pbuf[(w0 + 1) * 28 + j]
              + pbuf[(w0 + 2) * 28 + j] + pbuf[(w0 + 3) * 28 + j];
        }
        {
            const int n = lane + 32;                 // 32..63
            if (n < NPG) {
                const int j = n - 24;                // 8..25
                b = pbuf[4 * 28 + j] + pbuf[5 * 28 + j]
                  + pbuf[6 * 28 + j] + pbuf[7 * 28 + j];
            } else b = NEG;
        }
        float m = fmaxf(a, b);
        #pragma unroll
        for (int off = 16; off > 0; off >>= 1)
            m = fmaxf(m, __shfl_xor_sync(0xffffffffu, m, off));
        float ea = __expf(a - m);
        float eb = (lane + 32 < NPG) ? __expf(b - m) : 0.f;
        float s = ea + eb;
        #pragma unroll
        for (int off = 16; off > 0; off >>= 1)
            s += __shfl_xor_sync(0xffffffffu, s, off);
        const float inv = __fdividef(1.f, s);
        alpha_s[lane] = ea * inv;
        if (lane + 32 < NPG) alpha_s[lane + 32] = eb * inv;
        if (lane >= 18) alpha_s[lane + 32] = 0.f;   // pad 50..63
    }
    __syncthreads();

    // ---- readout: out[g][t] = sum_n alpha[n] * fT[t][n] ----
    {
        float r = 0.f;
        const float4* myrow = (const float4*)(fT + t * FSTR);
        const float4* al4   = (const float4*)alpha_s;
        #pragma unroll
        for (int jj = 0; jj < 12; ++jj) {
            float4 q = myrow[jj];
            float4 a = al4[jj];
            r += q.x * a.x + q.y * a.y + q.z * a.z + q.w * a.w;
        }
        r += fT[t * FSTR + 48] * alpha_s[48];
        r += fT[t * FSTR + 49] * alpha_s[49];
        out[(size_t)g * HCONST + t] = r;
    }
}

// ---------------------------------------------------------------------------
extern "C" void kernel_launch(void* const* d_in, const int* in_sizes, int n_in,
                              void* d_out, int out_size)
{
    const float* feat       = (const float*)d_in[0];
    const float* intend     = (const float*)d_in[1];
    const int*   last_nodes = (const int*)d_in[2];
    // d_in[3] segment_ids: unused (graphs are contiguous, equal-sized)
    const float* W_u  = (const float*)d_in[4];
    const float* W_v  = (const float*)d_in[5];
    const float* b_v  = (const float*)d_in[6];
    const float* W_i  = (const float*)d_in[7];
    const float* b_i  = (const float*)d_in[8];
    const float* W_e  = (const float*)d_in[9];
    const float* bn_g = (const float*)d_in[10];
    const float* bn_b = (const float*)d_in[11];
    const float* bn_m = (const float*)d_in[12];
    const float* bn_v = (const float*)d_in[13];
    float* out = (float*)d_out;

    const int B = in_sizes[1] / HCONST;   // 10000

    const size_t smem1 = (size_t)(2 * DCONST) * K1_STR * sizeof(float);  // ~72 KB
    const size_t smem2 = (size_t)(DCONST * FSTR + 8 * 28 + 64) * sizeof(float); // ~54.4 KB

    cudaFuncSetAttribute(pergraph_kernel,
                         cudaFuncAttributeMaxDynamicSharedMemorySize, (int)smem1);
    cudaFuncSetAttribute(attn_main_kernel,
                         cudaFuncAttributeMaxDynamicSharedMemorySize, (int)smem2);

    const int nblk1 = (B + K1_ROWS - 1) / K1_ROWS;
    pergraph_kernel<<<nblk1, 256, smem1>>>(feat, intend, last_nodes,
                                           W_v, b_v, W_i, b_i,
                                           bn_g, bn_b, bn_m, bn_v, B);

    attn_main_kernel<<<B, 256, smem2>>>(feat, W_u, W_e,
                                        bn_g, bn_b, bn_m, bn_v, out);
}

// round 16
// speedup vs baseline: 3.4065x; 2.3673x over previous
#include <cuda_runtime.h>
#include <cuda_bf16.h>
#include <cstdint>

// ---------------------------------------------------------------------------
// AttnReadout — R16: mma.sync (HMMA bf16, 3-way split) gate GEMM.
// tcgen05 is unavailable (harness emits compute_103 PTX, no 'a' features);
// mma.sync/ldmatrix are baseline PTX and still use the tensor pipe.
//   prep: W_u -> fragment-packed bf16 hi/lo images (uint2 per lane) in gmem.
//   K1:   p[g,h] = BN(feat[last[g]]) @ W_i + intend[g] @ W_v + b_i + b_v
//   K2:   per graph: A = split-bf16(BN(feat_g)) [64pad x 256] in smem;
//         u = A @ W_u via 768 mma.sync/warp; e = sigmoid(u+p)@W_e;
//         softmax(50); out = scale * (alpha^T feat) + shift.
// Shapes fixed: N=500000, B=10000, D=H=256, 50 nodes/graph.
// ---------------------------------------------------------------------------

#define DCONST 256
#define HCONST 256
#define NPG    50
#define MAXB   10000

__device__ float g_pg[MAXB * HCONST];     // per-graph gate vectors
__device__ uint2 g_Bpack[2 * 16 * 256 * 4];  // 256 KB: [split][ktile][n][kq]

// ---------------- small helpers ----------------
__device__ __forceinline__ uint32_t smem_to_u32(const void* p) {
    uint32_t a;
    asm("{ .reg .u64 t; cvta.to.shared.u64 t, %1; cvt.u32.u64 %0, t; }"
        : "=r"(a) : "l"(p));
    return a;
}
__device__ __forceinline__ void ldmatrix_x4(
    uint32_t& r0, uint32_t& r1, uint32_t& r2, uint32_t& r3, uint32_t addr)
{
    asm volatile("ldmatrix.sync.aligned.m8n8.x4.shared.b16 {%0,%1,%2,%3}, [%4];"
                 : "=r"(r0), "=r"(r1), "=r"(r2), "=r"(r3) : "r"(addr));
}
__device__ __forceinline__ void mma_bf16(
    float* c, const uint32_t* a, uint32_t b0, uint32_t b1)
{
    asm volatile(
        "mma.sync.aligned.m16n8k16.row.col.f32.bf16.bf16.f32 "
        "{%0,%1,%2,%3}, {%4,%5,%6,%7}, {%8,%9}, {%0,%1,%2,%3};"
        : "+f"(c[0]), "+f"(c[1]), "+f"(c[2]), "+f"(c[3])
        : "r"(a[0]), "r"(a[1]), "r"(a[2]), "r"(a[3]), "r"(b0), "r"(b1));
}

// ---------------------------------------------------------------------------
// prep: W_u[k][h] -> g_Bpack fragment layout.
// For m16n8k16 col B frag: lane(n = l>>2, q = l&3) needs k = {2q,2q+1} (.x)
// and {2q+8, 2q+9} (.y). uint2 index = ((split*16 + kt)*256 + h)*4 + q.
// ---------------------------------------------------------------------------
__global__ void prep_B_kernel(const float* __restrict__ W_u)
{
    const int k = blockIdx.x;      // 0..255
    const int h = threadIdx.x;     // 0..255
    const float w = W_u[k * HCONST + h];
    const __nv_bfloat16 hi = __float2bfloat16(w);
    const __nv_bfloat16 lo = __float2bfloat16(w - __bfloat162float(hi));
    const int kt   = k >> 4;
    const int kin  = k & 15;
    const int q    = (kin & 7) >> 1;
    const int widx = ((kin >> 3) << 1) | (kin & 1);   // ushort within uint2
    unsigned short* base = (unsigned short*)g_Bpack;
    const int u2_hi = ((kt * 256) + h) * 4 + q;
    base[u2_hi * 4 + widx]         = __bfloat16_as_ushort(hi);
    base[(65536 + u2_hi * 4) + widx] = __bfloat16_as_ushort(lo);  // +16384 uint2
}

// ---------------------------------------------------------------------------
// K1: per-graph gate vector (unchanged from R14 — passing)
// ---------------------------------------------------------------------------
#define K1_ROWS 32
#define K1_STR  36

__device__ __forceinline__ unsigned long long pk2(float lo, float hi) {
    unsigned long long r;
    asm("mov.b64 %0, {%1, %2};" : "=l"(r) : "f"(lo), "f"(hi));
    return r;
}
__device__ __forceinline__ void unpk2(unsigned long long v, float& lo, float& hi) {
    asm("mov.b64 {%0, %1}, %2;" : "=f"(lo), "=f"(hi) : "l"(v));
}
#define FMA2(acc, a, b) \
    asm("fma.rn.f32x2 %0, %1, %2, %0;" : "+l"(acc) : "l"(a), "l"(b))

__global__ void __launch_bounds__(256, 2) pergraph_kernel(
    const float* __restrict__ feat, const float* __restrict__ intend,
    const int* __restrict__ last_nodes,
    const float* __restrict__ W_v, const float* __restrict__ b_v,
    const float* __restrict__ W_i, const float* __restrict__ b_i,
    const float* __restrict__ bn_g, const float* __restrict__ bn_b,
    const float* __restrict__ bn_m, const float* __restrict__ bn_v,
    int B)
{
    extern __shared__ float sm[];
    float* AT = sm;

    const int t  = threadIdx.x;
    const int g0 = blockIdx.x * K1_ROWS;
    const int nrows = min(K1_ROWS, B - g0);

    {
        const float scale = bn_g[t] * rsqrtf(bn_v[t] + 1e-5f);
        const float shift = bn_b[t] - bn_m[t] * scale;
        for (int r = 0; r < K1_ROWS; ++r) {
            float fv = 0.f, iv = 0.f;
            if (r < nrows) {
                const int g = g0 + r;
                fv = feat[(size_t)last_nodes[g] * DCONST + t] * scale + shift;
                iv = intend[(size_t)g * DCONST + t];
            }
            AT[t * K1_STR + r]            = fv;
            AT[(DCONST + t) * K1_STR + r] = iv;
        }
    }
    __syncthreads();

    const int hh    = t & 127;
    const int half  = t >> 7;
    const int h0    = 2 * hh;
    const int rbase = half * 16;

    const float bias0 = b_i[h0]     + b_v[h0];
    const float bias1 = b_i[h0 + 1] + b_v[h0 + 1];

    unsigned long long acc0[8], acc1[8];
    {
        const unsigned long long b20 = pk2(bias0, bias0);
        const unsigned long long b21 = pk2(bias1, bias1);
        #pragma unroll
        for (int j = 0; j < 8; ++j) { acc0[j] = b20; acc1[j] = b21; }
    }
    {
        const float2* Wi2 = (const float2*)W_i;
        float2 wn = Wi2[hh];
        #pragma unroll 1
        for (int k = 0; k < DCONST; ++k) {
            const float2 w = wn;
            if (k + 1 < DCONST) wn = Wi2[(k + 1) * 128 + hh];
            const unsigned long long w20 = pk2(w.x, w.x);
            const unsigned long long w21 = pk2(w.y, w.y);
            const ulonglong2* row = (const ulonglong2*)(AT + k * K1_STR + rbase);
            #pragma unroll
            for (int jj = 0; jj < 4; ++jj) {
                ulonglong2 q = row[jj];
                FMA2(acc0[2 * jj],     q.x, w20);
                FMA2(acc1[2 * jj],     q.x, w21);
                FMA2(acc0[2 * jj + 1], q.y, w20);
                FMA2(acc1[2 * jj + 1], q.y, w21);
            }
        }
    }
    {
        const float2* Wv2 = (const float2*)W_v;
        float2 wn = Wv2[hh];
        #pragma unroll 1
        for (int k = 0; k < DCONST; ++k) {
            const float2 w = wn;
            if (k + 1 < DCONST) wn = Wv2[(k + 1) * 128 + hh];
            const unsigned long long w20 = pk2(w.x, w.x);
            const unsigned long long w21 = pk2(w.y, w.y);
            const ulonglong2* row = (const ulonglong2*)(AT + (DCONST + k) * K1_STR + rbase);
            #pragma unroll
            for (int jj = 0; jj < 4; ++jj) {
                ulonglong2 q = row[jj];
                FMA2(acc0[2 * jj],     q.x, w20);
                FMA2(acc1[2 * jj],     q.x, w21);
                FMA2(acc0[2 * jj + 1], q.y, w20);
                FMA2(acc1[2 * jj + 1], q.y, w21);
            }
        }
    }
    #pragma unroll
    for (int j = 0; j < 8; ++j) {
        float a0, b0, a1, b1;
        unpk2(acc0[j], a0, b0);
        unpk2(acc1[j], a1, b1);
        const int r = rbase + 2 * j;
        if (r < nrows)
            *(float2*)(g_pg + (size_t)(g0 + r) * HCONST + h0) = make_float2(a0, a1);
        if (r + 1 < nrows)
            *(float2*)(g_pg + (size_t)(g0 + r + 1) * HCONST + h0) = make_float2(b0, b1);
    }
}

// ---------------------------------------------------------------------------
// K2: tensor-core (mma.sync) fused kernel. 1 CTA = 1 graph, 256 threads.
// A in smem: 64 rows x 264 bf16 (528B stride, conflict-free ldmatrix),
// hi @ 0, lo @ 33792. MISC @ 67584: we(1KB), p(1KB), pbuf 64x8 f32(2KB),
// e(256B), alpha(256B). Total 72192 B -> 2 CTAs/SM.
// Warp w owns output cols [32w, 32w+32).
// ---------------------------------------------------------------------------
#define ASTR_B  528                 // A row stride in bytes
#define A_HI_OFF 0
#define A_LO_OFF 33792
#define MISC_OFF 67584
#define MO_WE    0
#define MO_P     1024
#define MO_PBUF  2048
#define MO_E     4096
#define MO_ALPHA 4352
#define SMEM_K2  (MISC_OFF + 4608)

__global__ void __launch_bounds__(256, 2) attn_tc_kernel(
    const float* __restrict__ feat, const float* __restrict__ W_e,
    const float* __restrict__ bn_g, const float* __restrict__ bn_b,
    const float* __restrict__ bn_m, const float* __restrict__ bn_v,
    float* __restrict__ out)
{
    extern __shared__ __align__(16) unsigned char smc[];
    const uint32_t smem_u32 = smem_to_u32(smc);
    float* we_s    = (float*)(smc + MISC_OFF + MO_WE);
    float* p_s     = (float*)(smc + MISC_OFF + MO_P);
    float* pbuf    = (float*)(smc + MISC_OFF + MO_PBUF);
    float* e_s     = (float*)(smc + MISC_OFF + MO_E);
    float* alpha_s = (float*)(smc + MISC_OFF + MO_ALPHA);

    const int t    = threadIdx.x;
    const int lane = t & 31;
    const int warp = t >> 5;
    const int g    = blockIdx.x;

    // ---- stage params + A fill (thread t = column h) ----
    const float sc = bn_g[t] * rsqrtf(bn_v[t] + 1e-5f);
    const float sh = bn_b[t] - bn_m[t] * sc;
    we_s[t] = W_e[t];
    p_s[t]  = g_pg[(size_t)g * HCONST + t];

    {
        const float* fbase = feat + (size_t)g * NPG * DCONST + t;
        unsigned short* ahi = (unsigned short*)(smc + A_HI_OFF);
        unsigned short* alo = (unsigned short*)(smc + A_LO_OFF);
        #pragma unroll
        for (int n = 0; n < NPG; ++n) {
            const float v = fmaf(fbase[n * DCONST], sc, sh);
            const __nv_bfloat16 hi = __float2bfloat16(v);
            const __nv_bfloat16 lo = __float2bfloat16(v - __bfloat162float(hi));
            ahi[n * 264 + t] = __bfloat16_as_ushort(hi);
            alo[n * 264 + t] = __bfloat16_as_ushort(lo);
        }
        // zero pad rows 50..63 (132 uint32 per row)
        for (int idx = t; idx < 14 * 132; idx += 256) {
            const int row = 50 + idx / 132;
            const int w32 = idx % 132;
            ((uint32_t*)(smc + A_HI_OFF + row * ASTR_B))[w32] = 0u;
            ((uint32_t*)(smc + A_LO_OFF + row * ASTR_B))[w32] = 0u;
        }
    }
    __syncthreads();

    // ---- GEMM: warp covers cols nbase..nbase+31, rows 0..63 ----
    const int nbase = warp * 32;
    float acc[4][4][4];
    #pragma unroll
    for (int m = 0; m < 4; ++m)
        #pragma unroll
        for (int n = 0; n < 4; ++n)
            #pragma unroll
            for (int c = 0; c < 4; ++c) acc[m][n][c] = 0.f;

    // per-lane ldmatrix offset within a 16x16 tile
    const int grp = lane >> 3, li = lane & 7;
    const uint32_t aoff = (uint32_t)(li + ((grp & 1) << 3)) * ASTR_B
                        + (uint32_t)((grp >> 1) << 3) * 2u;
    const uint32_t lm_hi = smem_u32 + A_HI_OFF + aoff;
    const uint32_t lm_lo = smem_u32 + A_LO_OFF + aoff;

    #pragma unroll 1
    for (int kt = 0; kt < 16; ++kt) {
        uint32_t ahi[4][4], alo[4][4];
        #pragma unroll
        for (int m = 0; m < 4; ++m) {
            const uint32_t base = (uint32_t)(m * 16) * ASTR_B + (uint32_t)kt * 32u;
            ldmatrix_x4(ahi[m][0], ahi[m][1], ahi[m][2], ahi[m][3], lm_hi + base);
            ldmatrix_x4(alo[m][0], alo[m][1], alo[m][2], alo[m][3], lm_lo + base);
        }
        uint2 bh[4], bl[4];
        #pragma unroll
        for (int n = 0; n < 4; ++n) {
            const int idx = kt * 1024 + (nbase + n * 8) * 4 + lane;
            bh[n] = g_Bpack[idx];
            bl[n] = g_Bpack[16384 + idx];
        }
        #pragma unroll
        for (int m = 0; m < 4; ++m)
            #pragma unroll
            for (int n = 0; n < 4; ++n) {
                mma_bf16(acc[m][n], ahi[m], bh[n].x, bh[n].y);
                mma_bf16(acc[m][n], ahi[m], bl[n].x, bl[n].y);
                mma_bf16(acc[m][n], alo[m], bh[n].x, bh[n].y);
            }
    }

    // ---- epilogue: e partials. acc[m][n]: c0/c1 row = m*16 + lane>>2,
    //      c2/c3 row +8; cols = nbase + n*8 + (lane&3)*2 + {0,1}. ----
    {
        float ep[8];
        #pragma unroll
        for (int m = 0; m < 4; ++m) {
            #pragma unroll
            for (int hf = 0; hf < 2; ++hf) {
                float s = 0.f;
                #pragma unroll
                for (int n = 0; n < 4; ++n) {
                    const int c0 = nbase + n * 8 + (lane & 3) * 2;
                    const float u0 = acc[m][n][hf * 2 + 0];
                    const float u1 = acc[m][n][hf * 2 + 1];
                    s += __fdividef(we_s[c0],     1.f + __expf(-(u0 + p_s[c0])));
                    s += __fdividef(we_s[c0 + 1], 1.f + __expf(-(u1 + p_s[c0 + 1])));
                }
                ep[m * 2 + hf] = s;
            }
        }
        #pragma unroll
        for (int off = 1; off <= 2; off <<= 1)
            #pragma unroll
            for (int j = 0; j < 8; ++j)
                ep[j] += __shfl_xor_sync(0xffffffffu, ep[j], off);
        if ((lane & 3) == 0) {
            const int r8 = lane >> 2;
            #pragma unroll
            for (int m = 0; m < 4; ++m)
                #pragma unroll
                for (int hf = 0; hf < 2; ++hf)
                    pbuf[(m * 16 + hf * 8 + r8) * 8 + warp] = ep[m * 2 + hf];
        }
    }
    __syncthreads();

    if (t < 64) {
        float s = 0.f;
        #pragma unroll
        for (int w = 0; w < 8; ++w) s += pbuf[t * 8 + w];
        e_s[t] = s;
    }
    __syncthreads();

    // ---- softmax over 50 (warp 0) ----
    if (warp == 0) {
        const float NEG = -3.402823466e38f;
        const float a = e_s[lane];
        const float b = (lane + 32 < NPG) ? e_s[lane + 32] : NEG;
        float m = fmaxf(a, b);
        #pragma unroll
        for (int off = 16; off > 0; off >>= 1)
            m = fmaxf(m, __shfl_xor_sync(0xffffffffu, m, off));
        const float ea = __expf(a - m);
        const float eb = (lane + 32 < NPG) ? __expf(b - m) : 0.f;
        float s = ea + eb;
        #pragma unroll
        for (int off = 16; off > 0; off >>= 1)
            s += __shfl_xor_sync(0xffffffffu, s, off);
        const float inv = __fdividef(1.f, s);
        alpha_s[lane] = ea * inv;
        if (lane + 32 < NPG) alpha_s[lane + 32] = eb * inv;
    }
    __syncthreads();

    // ---- readout: out[g][t] = sc * sum_n alpha[n]*feat[n][t] + sh ----
    {
        const float* fs = feat + (size_t)g * NPG * DCONST + t;
        float r = 0.f;
        #pragma unroll
        for (int n = 0; n < NPG; ++n)
            r += alpha_s[n] * fs[(size_t)n * DCONST];
        out[(size_t)g * HCONST + t] = fmaf(sc, r, sh);
    }
}

// ---------------------------------------------------------------------------
extern "C" void kernel_launch(void* const* d_in, const int* in_sizes, int n_in,
                              void* d_out, int out_size)
{
    const float* feat       = (const float*)d_in[0];
    const float* intend     = (const float*)d_in[1];
    const int*   last_nodes = (const int*)d_in[2];
    // d_in[3] segment_ids: unused (graphs contiguous, equal-sized)
    const float* W_u  = (const float*)d_in[4];
    const float* W_v  = (const float*)d_in[5];
    const float* b_v  = (const float*)d_in[6];
    const float* W_i  = (const float*)d_in[7];
    const float* b_i  = (const float*)d_in[8];
    const float* W_e  = (const float*)d_in[9];
    const float* bn_g = (const float*)d_in[10];
    const float* bn_b = (const float*)d_in[11];
    const float* bn_m = (const float*)d_in[12];
    const float* bn_v = (const float*)d_in[13];
    float* out = (float*)d_out;

    const int B = in_sizes[1] / HCONST;   // 10000

    const size_t smem1 = (size_t)(2 * DCONST) * K1_STR * sizeof(float);  // ~72 KB
    cudaFuncSetAttribute(pergraph_kernel,
                         cudaFuncAttributeMaxDynamicSharedMemorySize, (int)smem1);
    cudaFuncSetAttribute(attn_tc_kernel,
                         cudaFuncAttributeMaxDynamicSharedMemorySize, SMEM_K2);

    prep_B_kernel<<<256, 256>>>(W_u);

    const int nblk1 = (B + K1_ROWS - 1) / K1_ROWS;
    pergraph_kernel<<<nblk1, 256, smem1>>>(feat, intend, last_nodes,
                                           W_v, b_v, W_i, b_i,
                                           bn_g, bn_b, bn_m, bn_v, B);

    attn_tc_kernel<<<B, 256, SMEM_K2>>>(feat, W_e,
                                        bn_g, bn_b, bn_m, bn_v, out);
}